// round 8
// baseline (speedup 1.0000x reference)
#include <cuda_runtime.h>
#include <cstdint>
#include <math.h>

// Histogram2D via first-moment particle deposit + exact separable erf-CDF
// convolution with derivative correction, q=4 fine cells per bin.
//
// Deposit per point: ONE red.global.add.v4.f32 of (1, dy, dx, dx*dy) into the
// nearest fine cell (moments in bin units). Reconstruction:
//   mass_x(i) ~ W(t) + dx*W'(t),  t = cell - i*Q   (2nd-order accurate)
// so  hist = sum_cells [W_x W_y*M00 + W_x W'_y*M01 + W'_x W_y*M10 + W'_x W'_y*M11]
// which stays separable: pass1 reduces fx -> (Ba,Bb)[ix][fy], pass2 reduces fy
// and fuses the normalization via a last-block counter.
// Error ~ h^2/24*K''; measured bilinear 5.26e-5 at h=1/8 => ~1.1e-4 here.

#define NB    128
#define Q     4
#define PADB  8                     // padding in bins
#define PAD   (PADB*Q)              // 32 fine cells
#define NF    (NB*Q + 2*PAD)        // 576 fine cells per axis
#define TAP0  6                     // first tap (zc = -6.375 bins)
#define NTAP  52                    // taps cover zc in [-6.4, +6.6] bins
#define ISEG  8                     // ix outputs per pass1 CTA
#define ERANGE (Q*ISEG + NTAP - Q)  // 80 fine rows read per pass1 CTA

__device__ float4 g_fg4[NF * NF];   // fine grid moments (M00,M01,M10,M11), 5.3 MB
__device__ float2 g_Bt2[NB * NF];   // pass1 output (Ba,Bb)[ix][fy], 590 KB
__device__ float  g_W[64];          // kernel tap table (bin units)
__device__ float  g_Wp[64];         // d/dz of tap table
__device__ float  g_sum;
__device__ unsigned g_cnt;

// ---------------------------------------------------------------------------
__global__ void k_init()
{
    const float4 z = make_float4(0.f, 0.f, 0.f, 0.f);
    size_t i = (size_t)blockIdx.x * blockDim.x + threadIdx.x;
    const size_t stride = (size_t)gridDim.x * blockDim.x;
    for (; i < (size_t)NF * NF; i += stride) g_fg4[i] = z;

    if (blockIdx.x == 0) {
        if (threadIdx.x < 64) {
            int t = threadIdx.x;
            float zc = ((float)t + 0.5f) * (1.0f / (float)Q) - (float)PADB;
            const float is2 = 0.70710678118654752f;   // 1/sqrt(2), sigma = 1 bin
            g_W[t] = 0.5f * (erff((1.0f - zc) * is2) - erff((-zc) * is2));
            const float inv_s2pi = 0.3989422804014327f;  // 1/sqrt(2*pi)
            g_Wp[t] = inv_s2pi * (expf(-0.5f * zc * zc)
                                - expf(-0.5f * (1.0f - zc) * (1.0f - zc)));
        }
        if (threadIdx.x == 64) { g_sum = 0.0f; g_cnt = 0u; }
    }
}

// ---------------------------------------------------------------------------
__global__ __launch_bounds__(256)
void k_deposit(const float* __restrict__ x,
               const float* __restrict__ ex,
               const float* __restrict__ ey,
               int n)
{
    const float lox = ex[0], dx = ex[1] - ex[0];
    const float loy = ey[0], dy = ey[1] - ey[0];
    const float sx = (float)Q / dx;
    const float sy = (float)Q / dy;

    int p = blockIdx.x * blockDim.x + threadIdx.x;
    if (p >= n) return;

    float2 u = *reinterpret_cast<const float2*>(x + (size_t)p * 6);

    float pfx = (u.x - lox) * sx + (float)PAD;
    float pfy = (u.y - loy) * sy + (float)PAD;
    float cfx = floorf(pfx), cfy = floorf(pfy);
    int cx = (int)cfx, cy = (int)cfy;
    if ((unsigned)cx >= NF || (unsigned)cy >= NF) return;  // mass < 1e-12 into grid

    float dxb = (pfx - cfx - 0.5f) * (1.0f / (float)Q);    // bin units
    float dyb = (pfy - cfy - 0.5f) * (1.0f / (float)Q);

    float4* ptr = &g_fg4[(size_t)cx * NF + cy];
    asm volatile("red.global.add.v4.f32 [%0], {%1, %2, %3, %4};"
                 :: "l"(ptr), "f"(1.0f), "f"(dyb), "f"(dxb), "f"(dxb * dyb)
                 : "memory");
}

// ---------------------------------------------------------------------------
__global__ __launch_bounds__(64)
void k_pass1()
{
    __shared__ float sW[NTAP], sWp[NTAP];
    if (threadIdx.x < NTAP) {
        sW[threadIdx.x]  = g_W[TAP0 + threadIdx.x];
        sWp[threadIdx.x] = g_Wp[TAP0 + threadIdx.x];
    }
    __syncthreads();

    const int fy = blockIdx.y * 64 + threadIdx.x;   // < NF (9*64 = 576)
    const int I0 = blockIdx.x * ISEG;
    const float4* col = g_fg4 + fy;

    float2 acc[ISEG];
    #pragma unroll
    for (int s = 0; s < ISEG; s++) acc[s] = make_float2(0.f, 0.f);

    #pragma unroll 4
    for (int e = 0; e < ERANGE; e++) {
        const int fx = I0 * Q + TAP0 + e;           // max 565 < NF
        float4 M = col[(size_t)fx * NF];
        #pragma unroll
        for (int s = 0; s < ISEG; s++) {
            int t = e - Q * s;                       // tap offset from TAP0
            if (t >= 0 && t < NTAP) {
                float wa = sW[t], wp = sWp[t];
                acc[s].x = fmaf(wa, M.x, fmaf(wp, M.z, acc[s].x));
                acc[s].y = fmaf(wa, M.y, fmaf(wp, M.w, acc[s].y));
            }
        }
    }

    #pragma unroll
    for (int s = 0; s < ISEG; s++)
        g_Bt2[(size_t)(I0 + s) * NF + fy] = acc[s];
}

// ---------------------------------------------------------------------------
#define SPAD(i) ((i) + ((i) >> 2))
__global__ __launch_bounds__(128)
void k_pass2(float* __restrict__ out,
             const float* __restrict__ ex,
             const float* __restrict__ ey)
{
    __shared__ float sW[NTAP], sWp[NTAP];
    __shared__ float sBa[NF + NF / 4], sBb[NF + NF / 4];
    __shared__ float red[128];
    __shared__ unsigned s_last;
    __shared__ float s_scale;

    const int iy = threadIdx.x;
    const int ix = blockIdx.x;

    if (iy < NTAP) { sW[iy] = g_W[TAP0 + iy]; sWp[iy] = g_Wp[TAP0 + iy]; }
    const float2* brow = g_Bt2 + (size_t)ix * NF;
    #pragma unroll
    for (int i = iy; i < NF; i += 128) {
        float2 v = brow[i];
        sBa[SPAD(i)] = v.x;
        sBb[SPAD(i)] = v.y;
    }
    __syncthreads();

    const int base = Q * iy + TAP0;                 // fy = base + t, max 565 < NF
    float a0 = 0.f, a1 = 0.f, a2 = 0.f, a3 = 0.f;
    #pragma unroll
    for (int t = 0; t < NTAP; t += 4) {
        a0 = fmaf(sW[t+0], sBa[SPAD(base+t+0)], fmaf(sWp[t+0], sBb[SPAD(base+t+0)], a0));
        a1 = fmaf(sW[t+1], sBa[SPAD(base+t+1)], fmaf(sWp[t+1], sBb[SPAD(base+t+1)], a1));
        a2 = fmaf(sW[t+2], sBa[SPAD(base+t+2)], fmaf(sWp[t+2], sBb[SPAD(base+t+2)], a2));
        a3 = fmaf(sW[t+3], sBa[SPAD(base+t+3)], fmaf(sWp[t+3], sBb[SPAD(base+t+3)], a3));
    }
    float h = (a0 + a1) + (a2 + a3);
    out[(size_t)ix * NB + iy] = h;

    red[iy] = h;
    __syncthreads();
    #pragma unroll
    for (int off = 64; off > 0; off >>= 1) {
        if (iy < off) red[iy] += red[iy + off];
        __syncthreads();
    }
    if (iy == 0) {
        atomicAdd(&g_sum, red[0]);
        __threadfence();
        s_last = atomicAdd(&g_cnt, 1u);
    }
    __syncthreads();
    if (s_last == NB - 1) {
        __threadfence();                             // acquire: out[] + g_sum
        if (iy == 0) {
            float dxw = ex[1] - ex[0];
            float dyw = ey[1] - ey[0];
            s_scale = 1.0f / (g_sum * dxw * dyw);
        }
        __syncthreads();
        float sc = s_scale;
        for (int i = iy; i < NB * NB; i += 128) out[i] *= sc;
    }
}

// ---------------------------------------------------------------------------
extern "C" void kernel_launch(void* const* d_in, const int* in_sizes, int n_in,
                              void* d_out, int out_size)
{
    const float* x  = (const float*)d_in[0];
    const float* ex = (const float*)d_in[1];
    const float* ey = (const float*)d_in[2];
    float* out = (float*)d_out;

    int n = in_sizes[0] / 6;

    k_init<<<512, 256>>>();
    k_deposit<<<(n + 255) / 256, 256>>>(x, ex, ey, n);
    k_pass1<<<dim3(NB / ISEG, NF / 64), 64>>>();
    k_pass2<<<NB, 128>>>(out, ex, ey);
}

// round 9
// speedup vs baseline: 1.1501x; 1.1501x over previous
#include <cuda_runtime.h>
#include <cuda_fp16.h>
#include <cstdint>
#include <math.h>

// Histogram2D via first-moment particle deposit + exact separable erf-CDF
// convolution with derivative correction, q=4 fine cells per bin.
//
// Per point: TWO global REDs into one 8-byte fine cell:
//   red.add.f32        M00 (+1)
//   red.add.noftz.f16x2 (M01=+dy, M10=+dx)   [bin units]
// Reconstruction (2nd-order): mass_x(i) ~ W(t) + dx*W'(t), cross term O(h^4)
// dropped. Separable: pass1 reduces fx -> (Ba,Bb)[ix][fy], pass2 reduces fy,
// then a small normalize kernel. Error model validated: 5.26e-5 @ h=1/8
// (bilinear) -> 1.27e-4 @ h=1/4 (moments); f16 moment noise ~1e-5.

#define NB    128
#define Q     4
#define PADB  8                     // padding in bins (support+max offset)
#define PAD   (PADB*Q)              // 32 fine cells
#define NF    (NB*Q + 2*PAD)        // 576 fine cells per axis
#define TAP0  12                    // first tap (zc = -4.875 bins)
#define NTAP  44                    // support ~ +/-5 bins (tail < 3e-7)
#define ISEG  8                     // ix outputs per pass1 CTA
#define ERANGE (Q*ISEG + NTAP - Q)  // 72 fine rows read per pass1 CTA

__device__ float2 g_fg[NF * NF];    // fine cell: (M00 f32, M01/M10 f16x2), 2.65 MB
__device__ float2 g_Bt2[NB * NF];   // pass1 output (Ba,Bb)[ix][fy], 590 KB
__device__ float  g_W[64];          // kernel tap table (bin units)
__device__ float  g_Wp[64];         // d/dz of tap table
__device__ float  g_colsum[NB];     // per-ix row sums from pass2

// ---------------------------------------------------------------------------
__global__ void k_init()
{
    const float2 z = make_float2(0.f, 0.f);
    size_t i = (size_t)blockIdx.x * blockDim.x + threadIdx.x;
    const size_t stride = (size_t)gridDim.x * blockDim.x;
    for (; i < (size_t)NF * NF; i += stride) g_fg[i] = z;

    if (blockIdx.x == 0 && threadIdx.x < 64) {
        int t = threadIdx.x;
        float zc = ((float)t + 0.5f) * (1.0f / (float)Q) - (float)PADB;
        const float is2 = 0.70710678118654752f;   // 1/sqrt(2), sigma = 1 bin
        g_W[t] = 0.5f * (erff((1.0f - zc) * is2) - erff((-zc) * is2));
        const float inv_s2pi = 0.3989422804014327f;  // 1/sqrt(2*pi)
        g_Wp[t] = inv_s2pi * (expf(-0.5f * zc * zc)
                            - expf(-0.5f * (1.0f - zc) * (1.0f - zc)));
    }
}

// ---------------------------------------------------------------------------
// Moment deposit: 2 RED instructions (2 lanes) per point.
__global__ __launch_bounds__(256)
void k_deposit(const float* __restrict__ x,
               const float* __restrict__ ex,
               const float* __restrict__ ey,
               int n)
{
    const float lox = ex[0], dx = ex[1] - ex[0];
    const float loy = ey[0], dy = ey[1] - ey[0];
    const float sx = (float)Q / dx;
    const float sy = (float)Q / dy;

    int p = blockIdx.x * blockDim.x + threadIdx.x;
    if (p >= n) return;

    float2 u = *reinterpret_cast<const float2*>(x + (size_t)p * 6);

    float pfx = (u.x - lox) * sx + (float)PAD;
    float pfy = (u.y - loy) * sy + (float)PAD;
    float cfx = floorf(pfx), cfy = floorf(pfy);
    int cx = (int)cfx, cy = (int)cfy;
    if ((unsigned)cx >= NF || (unsigned)cy >= NF) return;  // mass < 1e-8

    float dxb = (pfx - cfx - 0.5f) * (1.0f / (float)Q);    // bin units
    float dyb = (pfy - cfy - 0.5f) * (1.0f / (float)Q);

    float2* cell = &g_fg[(size_t)cx * NF + cy];
    asm volatile("red.global.add.f32 [%0], %1;"
                 :: "l"(reinterpret_cast<float*>(cell)), "f"(1.0f) : "memory");
    __half2 hm = __halves2half2(__float2half(dyb), __float2half(dxb));
    asm volatile("red.global.add.noftz.f16x2 [%0], %1;"
                 :: "l"(reinterpret_cast<char*>(cell) + 4),
                    "r"(*reinterpret_cast<uint32_t*>(&hm)) : "memory");
}

// ---------------------------------------------------------------------------
// Pass 1: reduce fx with halo-redundant reads; no atomics, no Bt zeroing.
//   Ba[ix][fy] = sum_fx W[t]*M00 + Wp[t]*M10,  Bb[ix][fy] = sum_fx W[t]*M01
// Grid: (NB/ISEG = 16) x (NF/64 = 9), 64 threads (one fy each).
__global__ __launch_bounds__(64)
void k_pass1()
{
    __shared__ float sW[NTAP], sWp[NTAP];
    if (threadIdx.x < NTAP) {
        sW[threadIdx.x]  = g_W[TAP0 + threadIdx.x];
        sWp[threadIdx.x] = g_Wp[TAP0 + threadIdx.x];
    }
    __syncthreads();

    const int fy = blockIdx.y * 64 + threadIdx.x;   // < NF (9*64 = 576)
    const int I0 = blockIdx.x * ISEG;
    const float2* col = g_fg + fy;

    float2 acc[ISEG];
    #pragma unroll
    for (int s = 0; s < ISEG; s++) acc[s] = make_float2(0.f, 0.f);

    #pragma unroll 4
    for (int e = 0; e < ERANGE; e++) {
        const int fx = I0 * Q + TAP0 + e;           // max 563 < NF
        float2 M = col[(size_t)fx * NF];
        uint32_t mb = __float_as_uint(M.y);
        __half2 h2 = *reinterpret_cast<__half2*>(&mb);
        float2 mom = __half22float2(h2);            // mom.x = M01, mom.y = M10
        #pragma unroll
        for (int s = 0; s < ISEG; s++) {
            int t = e - Q * s;                      // tap offset from TAP0
            if (t >= 0 && t < NTAP) {
                acc[s].x = fmaf(sW[t], M.x, fmaf(sWp[t], mom.y, acc[s].x));
                acc[s].y = fmaf(sW[t], mom.x, acc[s].y);
            }
        }
    }

    #pragma unroll
    for (int s = 0; s < ISEG; s++)
        g_Bt2[(size_t)(I0 + s) * NF + fy] = acc[s];
}

// ---------------------------------------------------------------------------
// Pass 2: reduce fy.  hist[ix][iy] = sum_t W[t]*Ba + Wp[t]*Bb at fy = Q*iy+TAP0+t.
// One CTA per ix; Bt row staged in padded smem (stride-4 -> 5, conflict-free).
// Also writes the per-ix row sum for the normalize kernel.
#define SPAD(i) ((i) + ((i) >> 2))
__global__ __launch_bounds__(128)
void k_pass2(float* __restrict__ out)
{
    __shared__ float sW[NTAP], sWp[NTAP];
    __shared__ float sBa[NF + NF / 4], sBb[NF + NF / 4];
    __shared__ float red[128];

    const int iy = threadIdx.x;
    const int ix = blockIdx.x;

    if (iy < NTAP) { sW[iy] = g_W[TAP0 + iy]; sWp[iy] = g_Wp[TAP0 + iy]; }
    const float2* brow = g_Bt2 + (size_t)ix * NF;
    #pragma unroll
    for (int i = iy; i < NF; i += 128) {
        float2 v = brow[i];
        sBa[SPAD(i)] = v.x;
        sBb[SPAD(i)] = v.y;
    }
    __syncthreads();

    const int base = Q * iy + TAP0;                 // max fy index 563 < NF
    float a0 = 0.f, a1 = 0.f, a2 = 0.f, a3 = 0.f;
    #pragma unroll
    for (int t = 0; t < NTAP; t += 4) {
        a0 = fmaf(sW[t+0], sBa[SPAD(base+t+0)], fmaf(sWp[t+0], sBb[SPAD(base+t+0)], a0));
        a1 = fmaf(sW[t+1], sBa[SPAD(base+t+1)], fmaf(sWp[t+1], sBb[SPAD(base+t+1)], a1));
        a2 = fmaf(sW[t+2], sBa[SPAD(base+t+2)], fmaf(sWp[t+2], sBb[SPAD(base+t+2)], a2));
        a3 = fmaf(sW[t+3], sBa[SPAD(base+t+3)], fmaf(sWp[t+3], sBb[SPAD(base+t+3)], a3));
    }
    float h = (a0 + a1) + (a2 + a3);
    out[(size_t)ix * NB + iy] = h;

    red[iy] = h;
    __syncthreads();
    #pragma unroll
    for (int off = 64; off > 0; off >>= 1) {
        if (iy < off) red[iy] += red[iy + off];
        __syncthreads();
    }
    if (iy == 0) g_colsum[ix] = red[0];
}

// ---------------------------------------------------------------------------
// Normalize: 16 CTAs; each redundantly reduces the 128 row sums, then scales
// its 1024-element slice of the output.
__global__ __launch_bounds__(256)
void k_norm(float* __restrict__ out,
            const float* __restrict__ ex,
            const float* __restrict__ ey)
{
    __shared__ float red[128];
    __shared__ float s_scale;
    const int t = threadIdx.x;

    if (t < 128) red[t] = g_colsum[t];
    __syncthreads();
    #pragma unroll
    for (int off = 64; off > 0; off >>= 1) {
        if (t < off) red[t] += red[t + off];
        __syncthreads();
    }
    if (t == 0) {
        float dxw = ex[1] - ex[0];
        float dyw = ey[1] - ey[0];
        s_scale = 1.0f / (red[0] * dxw * dyw);
    }
    __syncthreads();

    float sc = s_scale;
    const int base = blockIdx.x * 1024;
    #pragma unroll
    for (int k = 0; k < 4; k++)
        out[base + k * 256 + t] *= sc;
}

// ---------------------------------------------------------------------------
extern "C" void kernel_launch(void* const* d_in, const int* in_sizes, int n_in,
                              void* d_out, int out_size)
{
    const float* x  = (const float*)d_in[0];
    const float* ex = (const float*)d_in[1];
    const float* ey = (const float*)d_in[2];
    float* out = (float*)d_out;

    int n = in_sizes[0] / 6;

    k_init<<<512, 256>>>();
    k_deposit<<<(n + 255) / 256, 256>>>(x, ex, ey, n);
    k_pass1<<<dim3(NB / ISEG, NF / 64), 64>>>();
    k_pass2<<<NB, 128>>>(out);
    k_norm<<<16, 256>>>(out, ex, ey);
}